// round 15
// baseline (speedup 1.0000x reference)
#include <cuda_runtime.h>

// Problem constants (match reference)
#define NB     4
#define HH     512
#define WW     512
#define KK     4
#define FMAX   200000
#define SIGMA  1e-4f
#define GAMMA  1e-4f
#define EPSV   1e-10f
#define ZNEAR  1.0f
#define ZFAR   100.0f

#define NPIX (NB * HH * WW)   // 1,048,576 == 4096 * 256 exactly

// 1/SIGMA and 1/GAMMA are exactly representable (10000.0f) -> mul == div.
#define INV_SG 10000.0f

// Weight cutoff: exp((zi-zmax)*1e4) < e^-40 ~ 4e-18 is < 1e-10 relative to the
// dominant weight (>= ~1e-7); the fp32 reference itself underflows to 0 below
// e^-87. Skipping these fragments skips their gather entirely.
#define Z_CUT  (40.0f / INV_SG)   // 0.004

// Prepass shape: small co-resident grid (~1.3 CTAs/SM) so the PDL secondary
// kernel's CTAs become resident immediately and phase 1 overlaps the prepass.
#define PRE_THREADS 256
#define FACES_PER_THREAD 4

// Packed per-face record: 32 bytes = ONE 32B L2 sector, loaded with a single
// 256-bit LDG.  a = (n0x,n0y,n0z,n1x), b = (n1y,n1z,n2x,n2y); the 32 bits of
// n2z are hidden in the low 4 mantissa bits of the 8 stored floats (nibble i
// in component i). n2z decode is bit-exact; carriers perturbed <=15 ulp.
struct __align__(32) FaceRec { float4 a, b; };
__device__ FaceRec g_facerec[FMAX];

__device__ __forceinline__ unsigned fb(float v) { return __float_as_uint(v); }

// 256-bit global load (sm_100+): one instruction, one sector per lane.
__device__ __forceinline__ void ldg256(const FaceRec* p, float4& a, float4& b) {
    asm("ld.global.nc.v8.f32 {%0,%1,%2,%3,%4,%5,%6,%7}, [%8];"
        : "=f"(a.x), "=f"(a.y), "=f"(a.z), "=f"(a.w),
          "=f"(b.x), "=f"(b.y), "=f"(b.z), "=f"(b.w)
        : "l"(p));
}

// Branchless gather of a 12B float3 at float-offset 3v using TWO aligned
// float2 loads (off = 3v - (v&1) is always even; both halves 8B-aligned and
// in-bounds for V=100000).
__device__ __forceinline__ float3 load_vn(const float* __restrict__ vn, int v) {
    const int off = 3 * v - (v & 1);
    const float2 A = __ldg((const float2*)vn + (off >> 1));
    const float2 B = __ldg((const float2*)vn + (off >> 1) + 1);
    const bool odd = (v & 1);
    float3 r;
    r.x = odd ? A.y : A.x;
    r.y = odd ? B.x : A.y;
    r.z = odd ? B.y : B.x;
    return r;
}

__device__ __forceinline__ void pack_store(int f, const float3& n0,
                                           const float3& n1, const float3& n2) {
    float c[8] = {n0.x, n0.y, n0.z, n1.x, n1.y, n1.z, n2.x, n2.y};
    const unsigned u = __float_as_uint(n2.z);
    #pragma unroll
    for (int i = 0; i < 8; i++) {
        unsigned bits = (__float_as_uint(c[i]) & ~0xFu) | ((u >> (4 * i)) & 0xFu);
        c[i] = __uint_as_float(bits);
    }
    FaceRec r;
    r.a = make_float4(c[0], c[1], c[2], c[3]);
    r.b = make_float4(c[4], c[5], c[6], c[7]);
    g_facerec[f] = r;
}

// 4 consecutive faces per thread: 3 aligned int4 loads + 12 vertex gathers.
__global__ __launch_bounds__(PRE_THREADS) void build_face_records(
    const float* __restrict__ vertex_normals,   // [V,3]
    const int*   __restrict__ faces,            // [F,3]
    int F)
{
    // Let the dependent (main) kernel launch immediately; it only consumes
    // g_facerec after cudaGridDependencySynchronize().
    cudaTriggerProgrammaticLaunchCompletion();

    const int t  = blockIdx.x * PRE_THREADS + threadIdx.x;
    const int f0 = t * FACES_PER_THREAD;
    if (f0 >= F) return;

    if (f0 + FACES_PER_THREAD <= F) {
        // fast path: 12 consecutive ints, 16B-aligned (48B per 4 faces)
        const int4* fp = (const int4*)(faces + 3 * f0);
        const int4 i0 = __ldg(fp + 0);
        const int4 i1 = __ldg(fp + 1);
        const int4 i2 = __ldg(fp + 2);
        const int v[12] = {i0.x, i0.y, i0.z, i0.w, i1.x, i1.y,
                           i1.z, i1.w, i2.x, i2.y, i2.z, i2.w};
        float3 n[12];
        #pragma unroll
        for (int i = 0; i < 12; i++)
            n[i] = load_vn(vertex_normals, v[i]);
        #pragma unroll
        for (int q = 0; q < 4; q++)
            pack_store(f0 + q, n[3 * q], n[3 * q + 1], n[3 * q + 2]);
    } else {
        for (int f = f0; f < F; f++) {
            const int v0 = __ldg(faces + 3 * f + 0);
            const int v1 = __ldg(faces + 3 * f + 1);
            const int v2 = __ldg(faces + 3 * f + 2);
            pack_store(f, load_vn(vertex_normals, v0),
                          load_vn(vertex_normals, v1),
                          load_vn(vertex_normals, v2));
        }
    }
}

__global__ __launch_bounds__(256) void normal_shader_kernel(
    const float* __restrict__ bary,             // [N,H,W,K,3]
    const float* __restrict__ dists,            // [N,H,W,K]
    const float* __restrict__ zbuf,             // [N,H,W,K]
    const int*   __restrict__ pix_to_face,      // [N,H,W,K]
    float*       __restrict__ out)              // [N,H,W,3]
{
    __shared__ float so[256 * 3];
    const int tid = threadIdx.x;
    const int p = blockIdx.x * 256 + tid;       // grid covers NPIX exactly

    // ================= PHASE 1 — independent of g_facerec =================
    // All coalesced streams + all math that doesn't need the face records.
    const int4   ptf = __ldg((const int4*)(pix_to_face) + p);
    const float4 zz  = __ldg((const float4*)(zbuf) + p);
    const float4 dd  = __ldg((const float4*)(dists) + p);
    const float4* bb = (const float4*)(bary + (size_t)p * 12);
    const float4 b0 = __ldg(bb + 0);
    const float4 b1 = __ldg(bb + 1);
    const float4 b2 = __ldg(bb + 2);

    const int   face[KK] = {ptf.x, ptf.y, ptf.z, ptf.w};
    const float zk[KK]   = {zz.x, zz.y, zz.z, zz.w};
    const float dk[KK]   = {dd.x, dd.y, dd.z, dd.w};
    const float bw[KK][3] = {
        {b0.x, b0.y, b0.z},
        {b0.w, b1.x, b1.y},
        {b1.z, b1.w, b2.x},
        {b2.y, b2.z, b2.w}
    };

    // zi MUST use exact IEEE div: 1 ulp amplifies ~1e4x in the exponent.
    float zinv[KK];
    float zmax = EPSV;
    #pragma unroll
    for (int k = 0; k < KK; k++) {
        const float zi = (face[k] >= 0) ? ((ZFAR - zk[k]) / (ZFAR - ZNEAR)) : 0.f;
        zinv[k] = zi;
        zmax = fmaxf(zmax, zi);
    }
    const float thr = zmax - Z_CUT;

    // Per-fragment softmax weights (0 for skipped fragments). All exp work
    // happens pre-sync so it overlaps the prepass.
    float wgt[KK];
    #pragma unroll
    for (int k = 0; k < KK; k++) {
        float w = 0.f;
        if (face[k] >= 0 && zinv[k] > thr) {
            // prob = sigmoid(-d/SIGMA)  (arg ~N(0,1); __expf err ~1e-6)
            const float pr = __fdividef(1.0f, 1.0f + __expf(dk[k] * INV_SG));
            w = pr * __expf((zinv[k] - zmax) * INV_SG);
        }
        wgt[k] = w;
    }

    // ================= PHASE 2 — needs the face records ====================
    cudaGridDependencySynchronize();

    float accx = 0.f, accy = 0.f, accz = 0.f, wsum = 0.f;
    #pragma unroll
    for (int k = 0; k < KK; k++) {
        if (wgt[k] != 0.f) {
            float4 a, b;
            ldg256(g_facerec + face[k], a, b);
            // reconstruct n2z from the 8 stolen nibbles (bit-exact)
            unsigned u =  (fb(a.x) & 0xFu)
                       | ((fb(a.y) & 0xFu) << 4)
                       | ((fb(a.z) & 0xFu) << 8)
                       | ((fb(a.w) & 0xFu) << 12)
                       | ((fb(b.x) & 0xFu) << 16)
                       | ((fb(b.y) & 0xFu) << 20)
                       | ((fb(b.z) & 0xFu) << 24)
                       | ((fb(b.w) & 0xFu) << 28);
            const float n2z = __uint_as_float(u);
            const float w0 = bw[k][0], w1 = bw[k][1], w2 = bw[k][2];
            const float w  = wgt[k];
            wsum += w;
            accx += w * (w0 * a.x + w1 * a.w + w2 * b.z);
            accy += w * (w0 * a.y + w1 * b.x + w2 * b.w);
            accz += w * (w0 * a.z + w1 * b.y + w2 * n2z);
        }
    }

    const float delta  = fmaxf(__expf((EPSV - zmax) * INV_SG), EPSV);
    const float rdenom = __fdividef(1.0f, wsum + delta);

    // bg = (1,1,1)
    float rx = (accx + delta) * rdenom;
    float ry = (accy + delta) * rdenom;
    float rz = (accz + delta) * rdenom;

    const float n2 = rx * rx + ry * ry + rz * rz;
    const float inv = (n2 > 1e-24f) ? rsqrtf(n2) : 1e12f;
    rx *= inv; ry *= inv; rz *= inv;

    // ---- coalesced store via smem staging (3 STG.128 wavefronts/warp) ----
    so[3 * tid + 0] = rx;
    so[3 * tid + 1] = ry;
    so[3 * tid + 2] = rz;
    __syncthreads();
    if (tid < 192) {
        float4* ob = (float4*)(out + (size_t)blockIdx.x * 768);
        const float4* sp = (const float4*)so;
        ob[tid] = sp[tid];
    }
}

extern "C" void kernel_launch(void* const* d_in, const int* in_sizes, int n_in,
                              void* d_out, int out_size)
{
    // metadata order: verts, vertex_normals, bary_coords, dists, zbuf, faces, pix_to_face
    const float* vertex_normals = (const float*)d_in[1];
    const float* bary           = (const float*)d_in[2];
    const float* dists          = (const float*)d_in[3];
    const float* zbuf           = (const float*)d_in[4];
    const int*   faces          = (const int*)d_in[5];
    const int*   pix_to_face    = (const int*)d_in[6];
    float*       out            = (float*)d_out;

    const int F = in_sizes[5] / 3;   // 200000

    // Primary: skinny prepass (~196 blocks, ~1.3 CTAs/SM) — co-resident with
    // the main grid so PDL actually overlaps.
    const int nthr = (F + FACES_PER_THREAD - 1) / FACES_PER_THREAD;
    build_face_records<<<(nthr + PRE_THREADS - 1) / PRE_THREADS, PRE_THREADS>>>(
        vertex_normals, faces, F);

    // Secondary: PDL — launches while prepass runs; phase 2 gated by
    // cudaGridDependencySynchronize().
    cudaLaunchConfig_t cfg = {};
    cfg.gridDim  = dim3(NPIX / 256, 1, 1);
    cfg.blockDim = dim3(256, 1, 1);
    cfg.dynamicSmemBytes = 0;
    cudaLaunchAttribute attr[1];
    attr[0].id = cudaLaunchAttributeProgrammaticStreamSerialization;
    attr[0].val.programmaticStreamSerializationAllowed = 1;
    cfg.attrs = attr;
    cfg.numAttrs = 1;
    cudaLaunchKernelEx(&cfg, normal_shader_kernel,
                       bary, dists, zbuf, pix_to_face, out);
}

// round 16
// speedup vs baseline: 1.0662x; 1.0662x over previous
#include <cuda_runtime.h>

// Problem constants (match reference)
#define NB     4
#define HH     512
#define WW     512
#define KK     4
#define FMAX   200000
#define SIGMA  1e-4f
#define GAMMA  1e-4f
#define EPSV   1e-10f
#define ZNEAR  1.0f
#define ZFAR   100.0f

#define NPIX (NB * HH * WW)   // 1,048,576 == 4096 * 256 exactly

// 1/SIGMA and 1/GAMMA are exactly representable (10000.0f) -> mul == div.
#define INV_SG 10000.0f

// Weight cutoff: exp((zi-zmax)*1e4) < e^-40 ~ 4e-18 is < 1e-10 relative to the
// dominant weight (>= ~1e-7); the fp32 reference itself underflows to 0 below
// e^-87. Skipping these fragments skips their gather entirely.
#define Z_CUT  (40.0f / INV_SG)   // 0.004

// Packed per-face record: 32 bytes = ONE 32B L2 sector, loaded with a single
// 256-bit LDG.  a = (n0x,n0y,n0z,n1x), b = (n1y,n1z,n2x,n2y); the 32 bits of
// n2z are hidden in the low 4 mantissa bits of the 8 stored floats (nibble i
// in component i). n2z decode is bit-exact; carriers perturbed <=15 ulp.
struct __align__(32) FaceRec { float4 a, b; };
__device__ FaceRec g_facerec[FMAX];

__device__ __forceinline__ unsigned fb(float v) { return __float_as_uint(v); }

// 256-bit global load (sm_100+): one instruction, one sector per lane.
__device__ __forceinline__ void ldg256(const FaceRec* p, float4& a, float4& b) {
    asm("ld.global.nc.v8.f32 {%0,%1,%2,%3,%4,%5,%6,%7}, [%8];"
        : "=f"(a.x), "=f"(a.y), "=f"(a.z), "=f"(a.w),
          "=f"(b.x), "=f"(b.y), "=f"(b.z), "=f"(b.w)
        : "l"(p));
}

// Gather of the 12B float3 at byte offset 12v with 1.5 loads/vertex average:
// one aligned float4 always; a predicated second float4 only when the normal
// crosses the 16B boundary (12v mod 16 >= 8, 50% of vertices).
// Bounds: second load issued only when rem4>=2; for v=99999 rem4==1 (no
// second load); for v<=99998 the second float4 ends <= byte 1,200,000. Safe.
__device__ __forceinline__ float3 load_vn(const float* __restrict__ vn, int v) {
    const unsigned B    = 12u * (unsigned)v;   // byte offset of the normal
    const unsigned q    = B >> 4;              // aligned float4 index
    const unsigned rem4 = (B & 12u) >> 2;      // float offset within q0: 0..3
    const float4 q0 = __ldg((const float4*)vn + q);
    float4 q1 = q0;
    if (rem4 >= 2)
        q1 = __ldg((const float4*)vn + q + 1);
    float3 r;
    r.x = (rem4 == 0) ? q0.x : (rem4 == 1) ? q0.y : (rem4 == 2) ? q0.z : q0.w;
    r.y = (rem4 == 0) ? q0.y : (rem4 == 1) ? q0.z : (rem4 == 2) ? q0.w : q1.x;
    r.z = (rem4 == 0) ? q0.z : (rem4 == 1) ? q0.w : (rem4 == 2) ? q1.x : q1.y;
    return r;
}

__global__ __launch_bounds__(256) void build_face_records(
    const float* __restrict__ vertex_normals,   // [V,3]
    const int*   __restrict__ faces,            // [F,3]
    int F)
{
    // PDL trigger (harmless if overlap doesn't materialize).
    cudaTriggerProgrammaticLaunchCompletion();

    int f = blockIdx.x * blockDim.x + threadIdx.x;
    if (f >= F) return;
    const int v0 = __ldg(faces + 3 * f + 0);
    const int v1 = __ldg(faces + 3 * f + 1);
    const int v2 = __ldg(faces + 3 * f + 2);
    const float3 n0 = load_vn(vertex_normals, v0);
    const float3 n1 = load_vn(vertex_normals, v1);
    const float3 n2 = load_vn(vertex_normals, v2);

    float c[8] = {n0.x, n0.y, n0.z, n1.x, n1.y, n1.z, n2.x, n2.y};
    const unsigned u = __float_as_uint(n2.z);
    #pragma unroll
    for (int i = 0; i < 8; i++) {
        unsigned bits = (__float_as_uint(c[i]) & ~0xFu) | ((u >> (4 * i)) & 0xFu);
        c[i] = __uint_as_float(bits);
    }

    FaceRec r;
    r.a = make_float4(c[0], c[1], c[2], c[3]);
    r.b = make_float4(c[4], c[5], c[6], c[7]);
    g_facerec[f] = r;
}

__global__ __launch_bounds__(256) void normal_shader_kernel(
    const float* __restrict__ bary,             // [N,H,W,K,3]
    const float* __restrict__ dists,            // [N,H,W,K]
    const float* __restrict__ zbuf,             // [N,H,W,K]
    const int*   __restrict__ pix_to_face,      // [N,H,W,K]
    float*       __restrict__ out)              // [N,H,W,3]
{
    __shared__ float so[256 * 3];
    const int tid = threadIdx.x;
    const int p = blockIdx.x * 256 + tid;       // grid covers NPIX exactly

    // ================= PHASE 1 — independent of g_facerec =================
    const int4   ptf = __ldg((const int4*)(pix_to_face) + p);
    const float4 zz  = __ldg((const float4*)(zbuf) + p);
    const float4 dd  = __ldg((const float4*)(dists) + p);
    const float4* bb = (const float4*)(bary + (size_t)p * 12);
    const float4 b0 = __ldg(bb + 0);
    const float4 b1 = __ldg(bb + 1);
    const float4 b2 = __ldg(bb + 2);

    const int   face[KK] = {ptf.x, ptf.y, ptf.z, ptf.w};
    const float zk[KK]   = {zz.x, zz.y, zz.z, zz.w};
    const float dk[KK]   = {dd.x, dd.y, dd.z, dd.w};
    const float bw[KK][3] = {
        {b0.x, b0.y, b0.z},
        {b0.w, b1.x, b1.y},
        {b1.z, b1.w, b2.x},
        {b2.y, b2.z, b2.w}
    };

    // zi MUST use exact IEEE div: 1 ulp amplifies ~1e4x in the exponent.
    float zinv[KK];
    float zmax = EPSV;
    #pragma unroll
    for (int k = 0; k < KK; k++) {
        const float zi = (face[k] >= 0) ? ((ZFAR - zk[k]) / (ZFAR - ZNEAR)) : 0.f;
        zinv[k] = zi;
        zmax = fmaxf(zmax, zi);
    }
    const float thr = zmax - Z_CUT;

    // Per-fragment softmax weights (0 for skipped fragments).
    float wgt[KK];
    #pragma unroll
    for (int k = 0; k < KK; k++) {
        float w = 0.f;
        if (face[k] >= 0 && zinv[k] > thr) {
            // prob = sigmoid(-d/SIGMA)  (arg ~N(0,1); __expf err ~1e-6)
            const float pr = __fdividef(1.0f, 1.0f + __expf(dk[k] * INV_SG));
            w = pr * __expf((zinv[k] - zmax) * INV_SG);
        }
        wgt[k] = w;
    }

    // ================= PHASE 2 — needs the face records ====================
    cudaGridDependencySynchronize();

    float accx = 0.f, accy = 0.f, accz = 0.f, wsum = 0.f;
    #pragma unroll
    for (int k = 0; k < KK; k++) {
        if (wgt[k] != 0.f) {
            float4 a, b;
            ldg256(g_facerec + face[k], a, b);
            // reconstruct n2z from the 8 stolen nibbles (bit-exact)
            unsigned u =  (fb(a.x) & 0xFu)
                       | ((fb(a.y) & 0xFu) << 4)
                       | ((fb(a.z) & 0xFu) << 8)
                       | ((fb(a.w) & 0xFu) << 12)
                       | ((fb(b.x) & 0xFu) << 16)
                       | ((fb(b.y) & 0xFu) << 20)
                       | ((fb(b.z) & 0xFu) << 24)
                       | ((fb(b.w) & 0xFu) << 28);
            const float n2z = __uint_as_float(u);
            const float w0 = bw[k][0], w1 = bw[k][1], w2 = bw[k][2];
            const float w  = wgt[k];
            wsum += w;
            accx += w * (w0 * a.x + w1 * a.w + w2 * b.z);
            accy += w * (w0 * a.y + w1 * b.x + w2 * b.w);
            accz += w * (w0 * a.z + w1 * b.y + w2 * n2z);
        }
    }

    const float delta  = fmaxf(__expf((EPSV - zmax) * INV_SG), EPSV);
    const float rdenom = __fdividef(1.0f, wsum + delta);

    // bg = (1,1,1)
    float rx = (accx + delta) * rdenom;
    float ry = (accy + delta) * rdenom;
    float rz = (accz + delta) * rdenom;

    const float n2 = rx * rx + ry * ry + rz * rz;
    const float inv = (n2 > 1e-24f) ? rsqrtf(n2) : 1e12f;
    rx *= inv; ry *= inv; rz *= inv;

    // ---- coalesced store via smem staging (3 STG.128 wavefronts/warp) ----
    so[3 * tid + 0] = rx;
    so[3 * tid + 1] = ry;
    so[3 * tid + 2] = rz;
    __syncthreads();
    if (tid < 192) {
        float4* ob = (float4*)(out + (size_t)blockIdx.x * 768);
        const float4* sp = (const float4*)so;
        ob[tid] = sp[tid];
    }
}

extern "C" void kernel_launch(void* const* d_in, const int* in_sizes, int n_in,
                              void* d_out, int out_size)
{
    // metadata order: verts, vertex_normals, bary_coords, dists, zbuf, faces, pix_to_face
    const float* vertex_normals = (const float*)d_in[1];
    const float* bary           = (const float*)d_in[2];
    const float* dists          = (const float*)d_in[3];
    const float* zbuf           = (const float*)d_in[4];
    const int*   faces          = (const int*)d_in[5];
    const int*   pix_to_face    = (const int*)d_in[6];
    float*       out            = (float*)d_out;

    const int F = in_sizes[5] / 3;   // 200000
    const int threads = 256;

    // Primary: prepass, 1 face/thread, full-wave shape (L1-wavefront bound —
    // wants many resident warps).
    build_face_records<<<(F + threads - 1) / threads, threads>>>(
        vertex_normals, faces, F);

    // Secondary: PDL attr kept (zero cost; phase 2 gated by grid-dep sync).
    cudaLaunchConfig_t cfg = {};
    cfg.gridDim  = dim3(NPIX / 256, 1, 1);
    cfg.blockDim = dim3(256, 1, 1);
    cfg.dynamicSmemBytes = 0;
    cudaLaunchAttribute attr[1];
    attr[0].id = cudaLaunchAttributeProgrammaticStreamSerialization;
    attr[0].val.programmaticStreamSerializationAllowed = 1;
    cfg.attrs = attr;
    cfg.numAttrs = 1;
    cudaLaunchKernelEx(&cfg, normal_shader_kernel,
                       bary, dists, zbuf, pix_to_face, out);
}